// round 2
// baseline (speedup 1.0000x reference)
#include <cuda_runtime.h>
#include <cuda_bf16.h>

// Cost volume: out[b,h,w,(9i+j)%81] = (1/H) * sum_c x1[b,h,w,c] * x2[b,h-i,w-j,c]
// B=8, H=W=C=128, sr=4, D=9, OC=81. Zero padding outside.
//
// Block = (b, band of 4 output rows). 256 threads = 128 w-lanes x 2 j-halves.
// Outer loop over 2 channel chunks of 64 (x1 band resident in SMEM per chunk);
// inner loop over the 12 x2 rows the band needs. Each staged x2 row is shared by
// up to 4 output rows. Results transposed through SMEM so stores are (w,j)-linear.
//
// Slot s = TOFF+t reads Bs[w+s] = x2[r][w+s-4]  =>  jj = 4 - s  (mirror! fixed in write-out).

#define Bb   8
#define Hh   128
#define Ww   128
#define Cc   128
#define SR   4
#define OC   81
#define RROWS 4          // output rows per block
#define CCH  64          // channels per chunk
#define CPAD 68          // padded chunk stride (68 mod 32 = 4 -> conflict-free float4 LDS)
#define WB   136         // x2 row width incl. +/-4 halo

#define AS_FLOATS (RROWS * Ww * CPAD)   // 4*128*68 = 34816
#define BS_FLOATS (WB * CPAD)           // 136*68  = 9248
#define CS_FLOATS (RROWS * Ww * 9)      // 4*128*9 = 4608
#define SMEM_FLOATS (AS_FLOATS + BS_FLOATS + CS_FLOATS)
#define SMEM_BYTES  (SMEM_FLOATS * 4)   // 194688 B

template<int NJ, int TOFF>
__device__ __forceinline__ void compute_rr(const float* __restrict__ As,
                                           const float* __restrict__ Bs,
                                           float* __restrict__ Cs,
                                           int w, int row_lo, int row_hi) {
    float acc[RROWS][NJ];
#pragma unroll
    for (int rw = 0; rw < RROWS; rw++)
#pragma unroll
        for (int t = 0; t < NJ; t++) acc[rw][t] = 0.0f;

#pragma unroll 4
    for (int c4 = 0; c4 < CCH / 4; c4++) {
        float4 bv[NJ];
#pragma unroll
        for (int t = 0; t < NJ; t++)
            bv[t] = *reinterpret_cast<const float4*>(Bs + (w + TOFF + t) * CPAD + (c4 << 2));
#pragma unroll
        for (int rw = 0; rw < RROWS; rw++) {
            if (rw >= row_lo && rw <= row_hi) {
                float4 a = *reinterpret_cast<const float4*>(As + (rw * Ww + w) * CPAD + (c4 << 2));
#pragma unroll
                for (int t = 0; t < NJ; t++) {
                    acc[rw][t] += a.x * bv[t].x;
                    acc[rw][t] += a.y * bv[t].y;
                    acc[rw][t] += a.z * bv[t].z;
                    acc[rw][t] += a.w * bv[t].w;
                }
            }
        }
    }
#pragma unroll
    for (int rw = 0; rw < RROWS; rw++) {
        if (rw >= row_lo && rw <= row_hi) {
#pragma unroll
            for (int t = 0; t < NJ; t++)
                Cs[(rw * Ww + w) * 9 + TOFF + t] = acc[rw][t];
        }
    }
}

__global__ void __launch_bounds__(256, 1)
cost_volume_kernel(const float* __restrict__ x1,
                   const float* __restrict__ x2,
                   float* __restrict__ out) {
    extern __shared__ float sm[];
    float* As = sm;                         // [4][128][68]
    float* Bs = sm + AS_FLOATS;             // [136][68]
    float* Cs = sm + AS_FLOATS + BS_FLOATS; // [4][128][9]

    const int tid  = threadIdx.x;
    const int w    = tid & 127;
    const int hg   = tid >> 7;              // slot groups: 0 -> s=0..4, 1 -> s=5..8
    const int bblk = blockIdx.x >> 5;       // batch
    const int h0   = (blockIdx.x & 31) << 2;
    const float invH = 1.0f / 128.0f;

    const float* x1b = x1 + ((size_t)(bblk * Hh + h0)) * (Ww * Cc);
    const float* x2b = x2 + ((size_t)bblk) * (Hh * Ww * Cc);
    float*       outb = out + ((size_t)(bblk * Hh + h0)) * (Ww * OC);

    for (int cc = 0; cc < 2; cc++) {
        const int c0 = cc << 6;
        __syncthreads();  // previous chunk's compute done before restaging As

        // Stage x1 band chunk: 4*128*16 float4s, 32 per thread, GMEM coalesced
        for (int idx = tid; idx < RROWS * Ww * (CCH / 4); idx += 256) {
            int row = idx >> 11;
            int rem = idx & 2047;
            int ww  = rem >> 4;
            int c4  = rem & 15;
            float4 v = *reinterpret_cast<const float4*>(
                x1b + (((row << 7) + ww) << 7) + c0 + (c4 << 2));
            *reinterpret_cast<float4*>(As + (row * Ww + ww) * CPAD + (c4 << 2)) = v;
        }

        for (int rr = 0; rr < 12; rr++) {
            const int r = h0 - 4 + rr;
            const bool rvalid = ((unsigned)r < (unsigned)Hh);
            const int row_lo = (rr - 8 > 0) ? rr - 8 : 0;
            const int row_hi = (rr < 3) ? rr : 3;

            __syncthreads();  // previous Bs/Cs consumers done (covers As stage at rr=0)

            if (rvalid) {
                // Stage x2 row r chunk with +/-4 halo, zero-filled at W edges
                for (int idx = tid; idx < WB * (CCH / 4); idx += 256) {
                    int wp = idx >> 4;
                    int c4 = idx & 15;
                    int w2 = wp - 4;
                    float4 v = make_float4(0.f, 0.f, 0.f, 0.f);
                    if ((unsigned)w2 < (unsigned)Ww)
                        v = *reinterpret_cast<const float4*>(
                            x2b + (((r << 7) + w2) << 7) + c0 + (c4 << 2));
                    *reinterpret_cast<float4*>(Bs + wp * CPAD + (c4 << 2)) = v;
                }
            }
            __syncthreads();

            if (rvalid) {
                if (hg == 0) compute_rr<5, 0>(As, Bs, Cs, w, row_lo, row_hi);
                else         compute_rr<4, 5>(As, Bs, Cs, w, row_lo, row_hi);
            }
            __syncthreads();

            // Write (near-coalesced) via Cs transpose buffer
            {
                const int nact  = row_hi - row_lo + 1;
                const int total = nact * Ww * 9;
                for (int idx = tid; idx < total; idx += 256) {
                    int rowl = idx / (Ww * 9);
                    int rem  = idx - rowl * (Ww * 9);
                    int ww   = rem / 9;
                    int s    = rem - ww * 9;          // slot index in Cs (0..8)
                    int row  = row_lo + rowl;
                    int ival = row + 4 - rr;          // i = h - r
                    int oc   = 9 * ival + (4 - s);    // jj = 4 - s  (slot mirror)
                    if (oc < 0) oc += OC;             // torch negative-index wrap
                    float v = rvalid ? Cs[(row * Ww + ww) * 9 + s] * invH : 0.0f;
                    float* o = outb + (size_t)(row * Ww + ww) * OC + oc;
                    if (cc == 0) *o = v;
                    else         *o += v;
                }
            }
        }
    }
}

extern "C" void kernel_launch(void* const* d_in, const int* in_sizes, int n_in,
                              void* d_out, int out_size) {
    const float* x1 = (const float*)d_in[0];
    const float* x2 = (const float*)d_in[1];
    float* out = (float*)d_out;

    static bool attr_set = false;
    if (!attr_set) {
        cudaFuncSetAttribute(cost_volume_kernel,
                             cudaFuncAttributeMaxDynamicSharedMemorySize, SMEM_BYTES);
        attr_set = true;
    }

    dim3 grid(Bb * (Hh / RROWS));  // 8 * 32 = 256 blocks
    cost_volume_kernel<<<grid, 256, SMEM_BYTES>>>(x1, x2, out);
}